// round 16
// baseline (speedup 1.0000x reference)
#include <cuda_runtime.h>
#include <cuda_bf16.h>
#include <cuda_fp16.h>
#include <math.h>

#define NN 100000
#define EE 1600000
#define FIN 512
#define H1 8
#define C1 8
#define HC 64
#define NC 40
#define ETOT (EE + NN)
#define NEG_SLOPE 0.2f
#define NBLK 98   // ceil(NN/1024)

// ---------------- scratch ----------------
__device__ unsigned short g_h1h[NN * HC];   // layer-1 features, fp16 (consumer: agg1)
__device__ unsigned short g_o1h[NN * HC];   // layer-1 output h2, fp16 (consumer: agg2)
__device__ float4 g_s4[NN * H1];            // {as, e^as, e^{0.2 as}, 0} per node/head
__device__ float4 g_d4[NN * H1];            // {ad, e^ad, e^{0.2 ad}, 0}
__device__ float4 g_s4b[NN];                // layer-2: {as2, e^as2, e^{0.2 as2}, 0}
__device__ float4 g_d4b[NN];
__device__ float g_ws[HC];                  // W2 @ a_src2
__device__ float g_wd[HC];                  // W2 @ a_dst2
__device__ int   g_src[ETOT];
__device__ int   g_dst[ETOT];
__device__ int   g_deg[NN];
__device__ int   g_row[NN + 1];
__device__ int   g_cursor[NN];
__device__ int   g_bsum[NBLK];
__device__ int   g_csr[ETOT];
__device__ int   g_is64 = 1;   // monotone flag, converges identically every call
__device__ unsigned short g_W1T_hi[HC * FIN];
__device__ unsigned short g_W1T_lo[HC * FIN];

__device__ __forceinline__ void split_bf16(float v, unsigned short& hi, unsigned short& lo) {
    __nv_bfloat16 h = __float2bfloat16(v);
    float r = v - __bfloat162float(h);
    __nv_bfloat16 l = __float2bfloat16(r);
    hi = __bfloat16_as_ushort(h);
    lo = __bfloat16_as_ushort(l);
}

__device__ __forceinline__ void mma_bf16(float* c, const unsigned* a, const unsigned* b) {
    asm volatile(
        "mma.sync.aligned.m16n8k16.row.col.f32.bf16.bf16.f32 "
        "{%0,%1,%2,%3},{%4,%5,%6,%7},{%8,%9},{%0,%1,%2,%3};"
        : "+f"(c[0]), "+f"(c[1]), "+f"(c[2]), "+f"(c[3])
        : "r"(a[0]), "r"(a[1]), "r"(a[2]), "r"(a[3]), "r"(b[0]), "r"(b[1]));
}

__device__ __forceinline__ void ldsm4(unsigned* r, unsigned addr) {
    asm volatile("ldmatrix.sync.aligned.m8n8.x4.shared.b16 {%0,%1,%2,%3}, [%4];"
                 : "=r"(r[0]), "=r"(r[1]), "=r"(r[2]), "=r"(r[3]) : "r"(addr));
}

// ---------------- init + dtype probe ----------------
__global__ void k_init(const void* __restrict__ ei) {
    int i = blockIdx.x * blockDim.x + threadIdx.x;
    if (i < NN) g_deg[i] = 0;
    if (i < 2048) {
        long long v = ((const long long*)ei)[i];
        if (v < 0 || v >= NN) atomicAnd(&g_is64, 0);
    }
}

// ---------------- edge conversion + degree count ----------------
__global__ void k_convert(const void* __restrict__ ei) {
    int idx = blockIdx.x * blockDim.x + threadIdx.x;
    if (idx >= ETOT) return;
    int s, d;
    if (idx < EE) {
        if (g_is64) {
            const long long* p = (const long long*)ei;
            s = (int)p[idx];
            d = (int)p[EE + idx];
        } else {
            const int* p = (const int*)ei;
            s = p[idx];
            d = p[EE + idx];
        }
    } else {
        s = d = idx - EE;
    }
    s = min(max(s, 0), NN - 1);
    d = min(max(d, 0), NN - 1);
    g_src[idx] = s;
    g_dst[idx] = d;
    atomicAdd(&g_deg[d], 1);
}

// ---------------- exclusive scan of degrees ----------------
__global__ void k_scan1() {
    __shared__ int sh[1024];
    int tid = threadIdx.x;
    int i = blockIdx.x * 1024 + tid;
    int v = (i < NN) ? g_deg[i] : 0;
    sh[tid] = v;
    __syncthreads();
    #pragma unroll
    for (int off = 1; off < 1024; off <<= 1) {
        int t = (tid >= off) ? sh[tid - off] : 0;
        __syncthreads();
        sh[tid] += t;
        __syncthreads();
    }
    if (i < NN) g_row[i] = sh[tid] - v;
    if (tid == 1023) g_bsum[blockIdx.x] = sh[1023];
}

__global__ void k_scan2() {
    if (threadIdx.x == 0) {
        int acc = 0;
        for (int b = 0; b < NBLK; b++) { int t = g_bsum[b]; g_bsum[b] = acc; acc += t; }
        g_row[NN] = acc;
    }
}

__global__ void k_scan3() {
    int i = blockIdx.x * blockDim.x + threadIdx.x;
    if (i < NN) {
        int r = g_row[i] + g_bsum[i >> 10];
        g_row[i] = r;
        g_cursor[i] = r;
    }
}

__global__ void k_scatter() {
    int idx = blockIdx.x * blockDim.x + threadIdx.x;
    if (idx >= ETOT) return;
    int d = g_dst[idx];
    int pos = atomicAdd(&g_cursor[d], 1);
    g_csr[pos] = g_src[idx];
}

// ---------------- W1 split/transpose ----------------
__global__ void k_prepW(const float* __restrict__ W1) {
    int i = blockIdx.x * blockDim.x + threadIdx.x;
    if (i >= FIN * HC) return;
    int k = i / HC, n = i % HC;
    unsigned short hi, lo;
    split_bf16(W1[i], hi, lo);
    g_W1T_hi[n * FIN + k] = hi;
    g_W1T_lo[n * FIN + k] = lo;
}

// ---------------- w_s = W2 @ a_src2, w_d = W2 @ a_dst2 ----------------
__global__ void k_wsd(const float* __restrict__ W2,
                      const float* __restrict__ a_s2, const float* __restrict__ a_d2) {
    int k = threadIdx.x;
    if (k < HC) {
        float s = 0.f, d = 0.f;
        #pragma unroll
        for (int c = 0; c < NC; c++) {
            float w = W2[k * NC + c];
            s = fmaf(w, a_s2[c], s);
            d = fmaf(w, a_d2[c], d);
        }
        g_ws[k] = s;
        g_wd[k] = d;
    }
}

// ---------------- GEMM1: bf16x3 tensor cores, ldmatrix, ping-pong pipeline ----------------
#define ASTR 40
#define ABYT (128 * ASTR * 2)
#define BBYT (64 * ASTR * 2)
#define OFF_AH(b) ((b) * ABYT)
#define OFF_AL(b) (2 * ABYT + (b) * ABYT)
#define OFF_BH(b) (4 * ABYT + (b) * BBYT)
#define OFF_BL(b) (4 * ABYT + 2 * BBYT + (b) * BBYT)
#define SMEM_G1  (4 * ABYT + 4 * BBYT)   // 61440 B

__global__ __launch_bounds__(256, 2) void k_gemm1(const float* __restrict__ x,
                                                  const float* __restrict__ a_s,
                                                  const float* __restrict__ a_d) {
    extern __shared__ __align__(16) char sm[];
    const unsigned smu = (unsigned)__cvta_generic_to_shared(sm);

    const int t = threadIdx.x;
    const int bm0 = blockIdx.x * 128;
    const int warp = t >> 5;
    const int lane = t & 31;
    const int g = lane >> 2;
    const int q = lane & 3;
    const int warp_m = warp >> 1;
    const int warp_n = warp & 1;
    const int brow = t >> 2;
    const int bseg = t & 3;

    const int mat = lane >> 3;
    const int rowin = lane & 7;
    const int lm_off = ((mat & 1) * 8 + rowin) * ASTR + (mat >> 1) * 8;

    float acc[2][4][4];
    #pragma unroll
    for (int i = 0; i < 2; i++)
        #pragma unroll
        for (int j = 0; j < 4; j++)
            #pragma unroll
            for (int r = 0; r < 4; r++) acc[i][j][r] = 0.f;

    float4 ra[4];
    uint4 rbh, rbl;

    auto load_regs = [&](int k0) {
        #pragma unroll
        for (int i = 0; i < 4; i++) {
            int idx = i * 256 + t;
            int row = idx >> 3;
            int col = (idx & 7) * 4;
            int gr = bm0 + row;
            ra[i] = (gr < NN) ? *(const float4*)(x + (long)gr * FIN + k0 + col)
                              : make_float4(0.f, 0.f, 0.f, 0.f);
        }
        rbh = *(const uint4*)&g_W1T_hi[brow * FIN + k0 + bseg * 8];
        rbl = *(const uint4*)&g_W1T_lo[brow * FIN + k0 + bseg * 8];
    };

    auto store_smem = [&](int b) {
        unsigned short* AsH = (unsigned short*)(sm + OFF_AH(b));
        unsigned short* AsL = (unsigned short*)(sm + OFF_AL(b));
        unsigned short* BsH = (unsigned short*)(sm + OFF_BH(b));
        unsigned short* BsL = (unsigned short*)(sm + OFF_BL(b));
        #pragma unroll
        for (int i = 0; i < 4; i++) {
            int idx = i * 256 + t;
            int row = idx >> 3;
            int col = (idx & 7) * 4;
            unsigned short h0, l0, h1_, l1_, h2, l2, h3, l3;
            split_bf16(ra[i].x, h0, l0);
            split_bf16(ra[i].y, h1_, l1_);
            split_bf16(ra[i].z, h2, l2);
            split_bf16(ra[i].w, h3, l3);
            unsigned* ph = (unsigned*)&AsH[row * ASTR + col];
            unsigned* pl = (unsigned*)&AsL[row * ASTR + col];
            ph[0] = (unsigned)h0 | ((unsigned)h1_ << 16);
            ph[1] = (unsigned)h2 | ((unsigned)h3 << 16);
            pl[0] = (unsigned)l0 | ((unsigned)l1_ << 16);
            pl[1] = (unsigned)l2 | ((unsigned)l3 << 16);
        }
        *(uint4*)&BsH[brow * ASTR + bseg * 8] = rbh;
        *(uint4*)&BsL[brow * ASTR + bseg * 8] = rbl;
    };

    load_regs(0);
    store_smem(0);

    for (int kt = 0; kt < FIN / 32; kt++) {
        const int cur = kt & 1;
        __syncthreads();
        if (kt + 1 < FIN / 32) load_regs((kt + 1) * 32);

        const unsigned ash = smu + OFF_AH(cur);
        const unsigned asl = smu + OFF_AL(cur);
        const unsigned bsh = smu + OFF_BH(cur);
        const unsigned bsl = smu + OFF_BL(cur);

        #pragma unroll
        for (int ka = 0; ka < 2; ka++) {
            const int kc = ka * 16;
            unsigned a_hi[2][4], a_lo[2][4], b_hi[4][2], b_lo[4][2];
            #pragma unroll
            for (int ma = 0; ma < 2; ma++) {
                int r0 = warp_m * 32 + ma * 16;
                unsigned eoff = (unsigned)((r0 * ASTR + kc + lm_off) * 2);
                ldsm4(a_hi[ma], ash + eoff);
                ldsm4(a_lo[ma], asl + eoff);
            }
            #pragma unroll
            for (int p = 0; p < 2; p++) {
                int n0 = warp_n * 32 + p * 16;
                unsigned eoff = (unsigned)((n0 * ASTR + kc + lm_off) * 2);
                unsigned rh[4], rl[4];
                ldsm4(rh, bsh + eoff);
                ldsm4(rl, bsl + eoff);
                b_hi[2 * p][0] = rh[0]; b_hi[2 * p][1] = rh[2];
                b_hi[2 * p + 1][0] = rh[1]; b_hi[2 * p + 1][1] = rh[3];
                b_lo[2 * p][0] = rl[0]; b_lo[2 * p][1] = rl[2];
                b_lo[2 * p + 1][0] = rl[1]; b_lo[2 * p + 1][1] = rl[3];
            }
            #pragma unroll
            for (int ma = 0; ma < 2; ma++)
                #pragma unroll
                for (int na = 0; na < 4; na++) {
                    mma_bf16(acc[ma][na], a_hi[ma], b_hi[na]);
                    mma_bf16(acc[ma][na], a_hi[ma], b_lo[na]);
                    mma_bf16(acc[ma][na], a_lo[ma], b_hi[na]);
                }
        }

        if (kt + 1 < FIN / 32) store_smem(cur ^ 1);
    }

    // ---- epilogue: write h1 as fp16 ----
    #pragma unroll
    for (int ma = 0; ma < 2; ma++) {
        int r0 = bm0 + warp_m * 32 + ma * 16 + g;
        #pragma unroll
        for (int na = 0; na < 4; na++) {
            int c = warp_n * 32 + na * 8 + 2 * q;
            if (r0 < NN)
                *(__half2*)(g_h1h + (long)r0 * HC + c) =
                    __floats2half2_rn(acc[ma][na][0], acc[ma][na][1]);
            if (r0 + 8 < NN)
                *(__half2*)(g_h1h + (long)(r0 + 8) * HC + c) =
                    __floats2half2_rn(acc[ma][na][2], acc[ma][na][3]);
        }
    }

    // ---- fused alpha1 + exp precompute ----
    float as_c0[4], as_c1[4], ad_c0[4], ad_c1[4];
    #pragma unroll
    for (int na = 0; na < 4; na++) {
        int hh = warp_n * 4 + na;
        as_c0[na] = a_s[hh * 8 + 2 * q];
        as_c1[na] = a_s[hh * 8 + 2 * q + 1];
        ad_c0[na] = a_d[hh * 8 + 2 * q];
        ad_c1[na] = a_d[hh * 8 + 2 * q + 1];
    }
    #pragma unroll
    for (int ma = 0; ma < 2; ma++)
        #pragma unroll
        for (int rh = 0; rh < 2; rh++) {
            float s[4], d[4];
            #pragma unroll
            for (int na = 0; na < 4; na++) {
                float h0 = acc[ma][na][rh * 2 + 0];
                float h1v = acc[ma][na][rh * 2 + 1];
                s[na] = h0 * as_c0[na] + h1v * as_c1[na];
                d[na] = h0 * ad_c0[na] + h1v * ad_c1[na];
            }
            #pragma unroll
            for (int na = 0; na < 4; na++) {
                s[na] += __shfl_xor_sync(0xffffffffu, s[na], 1);
                s[na] += __shfl_xor_sync(0xffffffffu, s[na], 2);
                d[na] += __shfl_xor_sync(0xffffffffu, d[na], 1);
                d[na] += __shfl_xor_sync(0xffffffffu, d[na], 2);
            }
            int row = bm0 + warp_m * 32 + ma * 16 + rh * 8 + g;
            if (q == 0 && row < NN) {
                #pragma unroll
                for (int na = 0; na < 4; na++) {
                    int hh = warp_n * 4 + na;
                    g_s4[row * H1 + hh] =
                        make_float4(s[na], __expf(s[na]), __expf(NEG_SLOPE * s[na]), 0.f);
                    g_d4[row * H1 + hh] =
                        make_float4(d[na], __expf(d[na]), __expf(NEG_SLOPE * d[na]), 0.f);
                }
            }
        }
}

// ---------------- layer-1 CSR aggregation + ELU + fused alpha2 (NO exp in loop) ----------------
__global__ void k_agg1(const float* __restrict__ b1) {
    int warp = (blockIdx.x * blockDim.x + threadIdx.x) >> 5;
    if (warp >= NN) return;
    int lane = threadIdx.x & 31;
    int qt = lane >> 3;
    int l = lane & 7;
    int n = warp;
    float4 dv = g_d4[n * H1 + l];
    const float adh = dv.x, c1 = dv.y, c2 = dv.z;
    int beg = g_row[n], end = g_row[n + 1];
    float sp = 0.f;
    float A[8] = {0.f, 0.f, 0.f, 0.f, 0.f, 0.f, 0.f, 0.f};

    int j = beg + qt;
    for (; j + 4 < end; j += 8) {
        int s0 = g_csr[j], s1 = g_csr[j + 4];
        float4 sv0 = g_s4[s0 * H1 + l];
        float4 sv1 = g_s4[s1 * H1 + l];
        uint4 u0 = *(const uint4*)(g_h1h + (long)s0 * HC + l * 8);
        uint4 u1 = *(const uint4*)(g_h1h + (long)s1 * HC + l * 8);
        float p0 = (sv0.x + adh > 0.f) ? sv0.y * c1 : sv0.z * c2;
        float p1 = (sv1.x + adh > 0.f) ? sv1.y * c1 : sv1.z * c2;
        sp += p0 + p1;
        const __half2* hp0 = (const __half2*)&u0;
        const __half2* hp1 = (const __half2*)&u1;
        #pragma unroll
        for (int w = 0; w < 4; w++) {
            float2 f0 = __half22float2(hp0[w]);
            float2 f1 = __half22float2(hp1[w]);
            A[2 * w + 0] = fmaf(p0, f0.x, A[2 * w + 0]);
            A[2 * w + 1] = fmaf(p0, f0.y, A[2 * w + 1]);
            A[2 * w + 0] = fmaf(p1, f1.x, A[2 * w + 0]);
            A[2 * w + 1] = fmaf(p1, f1.y, A[2 * w + 1]);
        }
    }
    for (; j < end; j += 4) {
        int s0 = g_csr[j];
        float4 sv0 = g_s4[s0 * H1 + l];
        uint4 u0 = *(const uint4*)(g_h1h + (long)s0 * HC + l * 8);
        float p0 = (sv0.x + adh > 0.f) ? sv0.y * c1 : sv0.z * c2;
        sp += p0;
        const __half2* hp0 = (const __half2*)&u0;
        #pragma unroll
        for (int w = 0; w < 4; w++) {
            float2 f0 = __half22float2(hp0[w]);
            A[2 * w + 0] = fmaf(p0, f0.x, A[2 * w + 0]);
            A[2 * w + 1] = fmaf(p0, f0.y, A[2 * w + 1]);
        }
    }
    #pragma unroll
    for (int i = 0; i < 8; i++) {
        A[i] += __shfl_xor_sync(0xffffffffu, A[i], 8);
        A[i] += __shfl_xor_sync(0xffffffffu, A[i], 16);
    }
    sp += __shfl_xor_sync(0xffffffffu, sp, 8);
    sp += __shfl_xor_sync(0xffffffffu, sp, 16);

    float inv = 1.0f / (sp + 1e-16f);
    float4 b0 = *(const float4*)(b1 + l * 8);
    float4 b1v = *(const float4*)(b1 + l * 8 + 4);
    float o[8];
    o[0] = A[0] * inv + b0.x; o[1] = A[1] * inv + b0.y;
    o[2] = A[2] * inv + b0.z; o[3] = A[3] * inv + b0.w;
    o[4] = A[4] * inv + b1v.x; o[5] = A[5] * inv + b1v.y;
    o[6] = A[6] * inv + b1v.z; o[7] = A[7] * inv + b1v.w;
    #pragma unroll
    for (int i = 0; i < 8; i++) o[i] = o[i] > 0.f ? o[i] : (expf(o[i]) - 1.f);

    if (qt == 0) {
        __half2 hv[4];
        #pragma unroll
        for (int w = 0; w < 4; w++) hv[w] = __floats2half2_rn(o[2 * w], o[2 * w + 1]);
        *(uint4*)(g_o1h + (long)n * HC + l * 8) = *(uint4*)hv;
    }

    // fused alpha2 + layer-2 exp precompute
    float ps = 0.f, pd = 0.f;
    #pragma unroll
    for (int i = 0; i < 8; i++) {
        ps = fmaf(o[i], g_ws[l * 8 + i], ps);
        pd = fmaf(o[i], g_wd[l * 8 + i], pd);
    }
    ps += __shfl_xor_sync(0xffffffffu, ps, 1);
    ps += __shfl_xor_sync(0xffffffffu, ps, 2);
    ps += __shfl_xor_sync(0xffffffffu, ps, 4);
    pd += __shfl_xor_sync(0xffffffffu, pd, 1);
    pd += __shfl_xor_sync(0xffffffffu, pd, 2);
    pd += __shfl_xor_sync(0xffffffffu, pd, 4);
    if (lane == 0) {
        g_s4b[n] = make_float4(ps, __expf(ps), __expf(NEG_SLOPE * ps), 0.f);
        g_d4b[n] = make_float4(pd, __expf(pd), __expf(NEG_SLOPE * pd), 0.f);
    }
}

// ---------------- layer-2 aggregation + matvec W2 + log_softmax (NO exp in loop) ----------------
__global__ void k_agg2(float* __restrict__ out, const float* __restrict__ b2,
                       const float* __restrict__ W2) {
    __shared__ float W2s[HC * NC];
    __shared__ float buf[8][HC];
    const int t = threadIdx.x;
    for (int i = t; i < HC * NC; i += 256) W2s[i] = W2[i];
    __syncthreads();

    int warp = (blockIdx.x * blockDim.x + t) >> 5;
    if (warp >= NN) return;
    int wloc = t >> 5;
    int lane = t & 31;
    int qt = lane >> 3;
    int l = lane & 7;
    int n = warp;
    float4 dv = g_d4b[n];
    const float ad = dv.x, c1 = dv.y, c2 = dv.z;
    int beg = g_row[n], end = g_row[n + 1];
    float sp = 0.f;
    float A[8] = {0.f, 0.f, 0.f, 0.f, 0.f, 0.f, 0.f, 0.f};

    int j = beg + qt;
    for (; j + 4 < end; j += 8) {
        int s0 = g_csr[j], s1 = g_csr[j + 4];
        float4 sv0 = g_s4b[s0];
        float4 sv1 = g_s4b[s1];
        uint4 u0 = *(const uint4*)(g_o1h + (long)s0 * HC + l * 8);
        uint4 u1 = *(const uint4*)(g_o1h + (long)s1 * HC + l * 8);
        float p0 = (sv0.x + ad > 0.f) ? sv0.y * c1 : sv0.z * c2;
        float p1 = (sv1.x + ad > 0.f) ? sv1.y * c1 : sv1.z * c2;
        sp += p0 + p1;
        const __half2* hp0 = (const __half2*)&u0;
        const __half2* hp1 = (const __half2*)&u1;
        #pragma unroll
        for (int w = 0; w < 4; w++) {
            float2 f0 = __half22float2(hp0[w]);
            float2 f1 = __half22float2(hp1[w]);
            A[2 * w + 0] = fmaf(p0, f0.x, A[2 * w + 0]);
            A[2 * w + 1] = fmaf(p0, f0.y, A[2 * w + 1]);
            A[2 * w + 0] = fmaf(p1, f1.x, A[2 * w + 0]);
            A[2 * w + 1] = fmaf(p1, f1.y, A[2 * w + 1]);
        }
    }
    for (; j < end; j += 4) {
        int s0 = g_csr[j];
        float4 sv0 = g_s4b[s0];
        uint4 u0 = *(const uint4*)(g_o1h + (long)s0 * HC + l * 8);
        float p0 = (sv0.x + ad > 0.f) ? sv0.y * c1 : sv0.z * c2;
        sp += p0;
        const __half2* hp0 = (const __half2*)&u0;
        #pragma unroll
        for (int w = 0; w < 4; w++) {
            float2 f0 = __half22float2(hp0[w]);
            A[2 * w + 0] = fmaf(p0, f0.x, A[2 * w + 0]);
            A[2 * w + 1] = fmaf(p0, f0.y, A[2 * w + 1]);
        }
    }
    #pragma unroll
    for (int i = 0; i < 8; i++) {
        A[i] += __shfl_xor_sync(0xffffffffu, A[i], 8);
        A[i] += __shfl_xor_sync(0xffffffffu, A[i], 16);
    }
    sp += __shfl_xor_sync(0xffffffffu, sp, 8);
    sp += __shfl_xor_sync(0xffffffffu, sp, 16);

    float inv = 1.0f / (sp + 1e-16f);
    if (lane < 8) {
        #pragma unroll
        for (int i = 0; i < 8; i++) buf[wloc][l * 8 + i] = A[i] * inv;
    }
    __syncwarp();

    float va = 0.f, vb = 0.f;
    #pragma unroll 8
    for (int k = 0; k < HC; k++) {
        float bk = buf[wloc][k];
        va = fmaf(bk, W2s[k * NC + lane], va);
        if (lane < 8) vb = fmaf(bk, W2s[k * NC + 32 + lane], vb);
    }
    va += b2[lane];
    vb = (lane < 8) ? vb + b2[32 + lane] : -3.402823466e38f;

    float m = fmaxf(va, vb);
    #pragma unroll
    for (int off = 16; off > 0; off >>= 1)
        m = fmaxf(m, __shfl_xor_sync(0xffffffffu, m, off));
    float s = expf(va - m) + ((lane < 8) ? expf(vb - m) : 0.f);
    #pragma unroll
    for (int off = 16; off > 0; off >>= 1)
        s += __shfl_xor_sync(0xffffffffu, s, off);
    float lse = m + logf(s);
    float* op = out + (long)n * NC;
    op[lane] = va - lse;
    if (lane < 8) op[32 + lane] = vb - lse;
}

// ---------------- launch: fork-join two independent chains ----------------
extern "C" void kernel_launch(void* const* d_in, const int* in_sizes, int n_in,
                              void* d_out, int out_size) {
    const float* x    = (const float*)d_in[0];
    const void*  ei   = d_in[1];
    const float* W1   = (const float*)d_in[2];
    const float* as1  = (const float*)d_in[3];
    const float* ad1  = (const float*)d_in[4];
    const float* b1   = (const float*)d_in[5];
    const float* W2   = (const float*)d_in[6];
    const float* as2  = (const float*)d_in[7];
    const float* ad2  = (const float*)d_in[8];
    const float* b2   = (const float*)d_in[9];
    float*       out  = (float*)d_out;

    static cudaStream_t s2 = 0;
    static cudaEvent_t evFork = 0, evJoin = 0;
    if (s2 == 0) {
        cudaStreamCreateWithFlags(&s2, cudaStreamNonBlocking);
        cudaEventCreateWithFlags(&evFork, cudaEventDisableTiming);
        cudaEventCreateWithFlags(&evJoin, cudaEventDisableTiming);
        cudaFuncSetAttribute(k_gemm1, cudaFuncAttributeMaxDynamicSharedMemorySize, SMEM_G1);
    }

    const int TB = 256;

    // fork
    cudaEventRecord(evFork, 0);
    cudaStreamWaitEvent(s2, evFork, 0);

    // chain B (side stream): CSR build
    k_init   <<<(NN + TB - 1) / TB, TB, 0, s2>>>(ei);
    k_convert<<<(ETOT + TB - 1) / TB, TB, 0, s2>>>(ei);
    k_scan1  <<<NBLK, 1024, 0, s2>>>();
    k_scan2  <<<1, 32, 0, s2>>>();
    k_scan3  <<<(NN + TB - 1) / TB, TB, 0, s2>>>();
    k_scatter<<<(ETOT + TB - 1) / TB, TB, 0, s2>>>();
    cudaEventRecord(evJoin, s2);

    // chain A (origin stream): dense transform, concurrent with chain B
    k_prepW  <<<(FIN * HC + TB - 1) / TB, TB>>>(W1);
    k_wsd    <<<1, 64>>>(W2, as2, ad2);
    k_gemm1  <<<(NN + 127) / 128, 256, SMEM_G1>>>(x, as1, ad1);

    // join
    cudaStreamWaitEvent(0, evJoin, 0);

    // serial tail
    k_agg1   <<<(NN * 32 + TB - 1) / TB, TB>>>(b1);
    k_agg2   <<<(NN * 32 + TB - 1) / TB, TB>>>(out, b2, W2);
}

// round 17
// speedup vs baseline: 1.1175x; 1.1175x over previous
#include <cuda_runtime.h>
#include <cuda_bf16.h>
#include <cuda_fp16.h>
#include <math.h>

#define NN 100000
#define EE 1600000
#define FIN 512
#define H1 8
#define C1 8
#define HC 64
#define NC 40
#define ETOT (EE + NN)
#define NEG_SLOPE 0.2f
#define NBLK 98   // ceil(NN/1024)

// ---------------- scratch ----------------
__device__ unsigned short g_h1h[NN * HC];   // layer-1 features, fp16 (consumer: agg1)
__device__ unsigned short g_o1h[NN * HC];   // layer-1 output h2, fp16 (consumer: agg2)
__device__ float g_as1[NN * H1];
__device__ float g_ad1[NN * H1];
__device__ float g_as2[NN];
__device__ float g_ad2[NN];
__device__ float g_ws[HC];                  // W2 @ a_src2
__device__ float g_wd[HC];                  // W2 @ a_dst2
__device__ int   g_src[ETOT];
__device__ int   g_dst[ETOT];
__device__ int   g_deg[NN];
__device__ int   g_row[NN + 1];
__device__ int   g_cursor[NN];
__device__ int   g_bsum[NBLK];
__device__ int   g_csr[ETOT];
__device__ int   g_is64 = 1;   // monotone flag, converges identically every call
__device__ unsigned short g_W1T_hi[HC * FIN];
__device__ unsigned short g_W1T_lo[HC * FIN];

__device__ __forceinline__ float lrelu(float x) {
    return x > 0.0f ? x : NEG_SLOPE * x;
}

__device__ __forceinline__ void split_bf16(float v, unsigned short& hi, unsigned short& lo) {
    __nv_bfloat16 h = __float2bfloat16(v);
    float r = v - __bfloat162float(h);
    __nv_bfloat16 l = __float2bfloat16(r);
    hi = __bfloat16_as_ushort(h);
    lo = __bfloat16_as_ushort(l);
}

__device__ __forceinline__ void mma_bf16(float* c, const unsigned* a, const unsigned* b) {
    asm volatile(
        "mma.sync.aligned.m16n8k16.row.col.f32.bf16.bf16.f32 "
        "{%0,%1,%2,%3},{%4,%5,%6,%7},{%8,%9},{%0,%1,%2,%3};"
        : "+f"(c[0]), "+f"(c[1]), "+f"(c[2]), "+f"(c[3])
        : "r"(a[0]), "r"(a[1]), "r"(a[2]), "r"(a[3]), "r"(b[0]), "r"(b[1]));
}

__device__ __forceinline__ void ldsm4(unsigned* r, unsigned addr) {
    asm volatile("ldmatrix.sync.aligned.m8n8.x4.shared.b16 {%0,%1,%2,%3}, [%4];"
                 : "=r"(r[0]), "=r"(r[1]), "=r"(r[2]), "=r"(r[3]) : "r"(addr));
}

// ---------------- init + dtype probe ----------------
__global__ void k_init(const void* __restrict__ ei) {
    int i = blockIdx.x * blockDim.x + threadIdx.x;
    if (i < NN) g_deg[i] = 0;
    if (i < 2048) {
        long long v = ((const long long*)ei)[i];
        if (v < 0 || v >= NN) atomicAnd(&g_is64, 0);
    }
}

// ---------------- edge conversion + degree count ----------------
__global__ void k_convert(const void* __restrict__ ei) {
    int idx = blockIdx.x * blockDim.x + threadIdx.x;
    if (idx >= ETOT) return;
    int s, d;
    if (idx < EE) {
        if (g_is64) {
            const long long* p = (const long long*)ei;
            s = (int)p[idx];
            d = (int)p[EE + idx];
        } else {
            const int* p = (const int*)ei;
            s = p[idx];
            d = p[EE + idx];
        }
    } else {
        s = d = idx - EE;
    }
    s = min(max(s, 0), NN - 1);
    d = min(max(d, 0), NN - 1);
    g_src[idx] = s;
    g_dst[idx] = d;
    atomicAdd(&g_deg[d], 1);
}

// ---------------- exclusive scan of degrees ----------------
__global__ void k_scan1() {
    __shared__ int sh[1024];
    int tid = threadIdx.x;
    int i = blockIdx.x * 1024 + tid;
    int v = (i < NN) ? g_deg[i] : 0;
    sh[tid] = v;
    __syncthreads();
    #pragma unroll
    for (int off = 1; off < 1024; off <<= 1) {
        int t = (tid >= off) ? sh[tid - off] : 0;
        __syncthreads();
        sh[tid] += t;
        __syncthreads();
    }
    if (i < NN) g_row[i] = sh[tid] - v;
    if (tid == 1023) g_bsum[blockIdx.x] = sh[1023];
}

__global__ void k_scan2() {
    if (threadIdx.x == 0) {
        int acc = 0;
        for (int b = 0; b < NBLK; b++) { int t = g_bsum[b]; g_bsum[b] = acc; acc += t; }
        g_row[NN] = acc;
    }
}

__global__ void k_scan3() {
    int i = blockIdx.x * blockDim.x + threadIdx.x;
    if (i < NN) {
        int r = g_row[i] + g_bsum[i >> 10];
        g_row[i] = r;
        g_cursor[i] = r;
    }
}

__global__ void k_scatter() {
    int idx = blockIdx.x * blockDim.x + threadIdx.x;
    if (idx >= ETOT) return;
    int d = g_dst[idx];
    int pos = atomicAdd(&g_cursor[d], 1);
    g_csr[pos] = g_src[idx];
}

// ---------------- W1 split/transpose + fused w_s/w_d precompute ----------------
__global__ void k_prepW(const float* __restrict__ W1, const float* __restrict__ W2,
                        const float* __restrict__ a_s2, const float* __restrict__ a_d2) {
    int i = blockIdx.x * blockDim.x + threadIdx.x;
    if (i < FIN * HC) {
        int k = i / HC, n = i % HC;
        unsigned short hi, lo;
        split_bf16(W1[i], hi, lo);
        g_W1T_hi[n * FIN + k] = hi;
        g_W1T_lo[n * FIN + k] = lo;
    }
    // block 0, lanes 0..63: fold layer-2 logits  w_s = W2 a_s2, w_d = W2 a_d2
    if (blockIdx.x == 0 && threadIdx.x < HC) {
        int k = threadIdx.x;
        float s = 0.f, d = 0.f;
        #pragma unroll
        for (int c = 0; c < NC; c++) {
            float w = W2[k * NC + c];
            s = fmaf(w, a_s2[c], s);
            d = fmaf(w, a_d2[c], d);
        }
        g_ws[k] = s;
        g_wd[k] = d;
    }
}

// ---------------- GEMM1: bf16x3 tensor cores, ldmatrix, ping-pong pipeline ----------------
#define ASTR 40
#define ABYT (128 * ASTR * 2)   // 10240 B per A buffer
#define BBYT (64 * ASTR * 2)    // 5120 B per B buffer
#define OFF_AH(b) ((b) * ABYT)
#define OFF_AL(b) (2 * ABYT + (b) * ABYT)
#define OFF_BH(b) (4 * ABYT + (b) * BBYT)
#define OFF_BL(b) (4 * ABYT + 2 * BBYT + (b) * BBYT)
#define SMEM_G1  (4 * ABYT + 4 * BBYT)   // 61440 B

__global__ __launch_bounds__(256, 2) void k_gemm1(const float* __restrict__ x,
                                                  const float* __restrict__ a_s,
                                                  const float* __restrict__ a_d) {
    extern __shared__ __align__(16) char sm[];
    const unsigned smu = (unsigned)__cvta_generic_to_shared(sm);

    const int t = threadIdx.x;
    const int bm0 = blockIdx.x * 128;
    const int warp = t >> 5;
    const int lane = t & 31;
    const int g = lane >> 2;
    const int q = lane & 3;
    const int warp_m = warp >> 1;
    const int warp_n = warp & 1;
    const int brow = t >> 2;
    const int bseg = t & 3;

    const int mat = lane >> 3;
    const int rowin = lane & 7;
    const int lm_off = ((mat & 1) * 8 + rowin) * ASTR + (mat >> 1) * 8;  // elements

    float acc[2][4][4];
    #pragma unroll
    for (int i = 0; i < 2; i++)
        #pragma unroll
        for (int j = 0; j < 4; j++)
            #pragma unroll
            for (int r = 0; r < 4; r++) acc[i][j][r] = 0.f;

    float4 ra[4];
    uint4 rbh, rbl;

    auto load_regs = [&](int k0) {
        #pragma unroll
        for (int i = 0; i < 4; i++) {
            int idx = i * 256 + t;
            int row = idx >> 3;
            int col = (idx & 7) * 4;
            int gr = bm0 + row;
            ra[i] = (gr < NN) ? *(const float4*)(x + (long)gr * FIN + k0 + col)
                              : make_float4(0.f, 0.f, 0.f, 0.f);
        }
        rbh = *(const uint4*)&g_W1T_hi[brow * FIN + k0 + bseg * 8];
        rbl = *(const uint4*)&g_W1T_lo[brow * FIN + k0 + bseg * 8];
    };

    auto store_smem = [&](int b) {
        unsigned short* AsH = (unsigned short*)(sm + OFF_AH(b));
        unsigned short* AsL = (unsigned short*)(sm + OFF_AL(b));
        unsigned short* BsH = (unsigned short*)(sm + OFF_BH(b));
        unsigned short* BsL = (unsigned short*)(sm + OFF_BL(b));
        #pragma unroll
        for (int i = 0; i < 4; i++) {
            int idx = i * 256 + t;
            int row = idx >> 3;
            int col = (idx & 7) * 4;
            unsigned short h0, l0, h1_, l1_, h2, l2, h3, l3;
            split_bf16(ra[i].x, h0, l0);
            split_bf16(ra[i].y, h1_, l1_);
            split_bf16(ra[i].z, h2, l2);
            split_bf16(ra[i].w, h3, l3);
            unsigned* ph = (unsigned*)&AsH[row * ASTR + col];
            unsigned* pl = (unsigned*)&AsL[row * ASTR + col];
            ph[0] = (unsigned)h0 | ((unsigned)h1_ << 16);
            ph[1] = (unsigned)h2 | ((unsigned)h3 << 16);
            pl[0] = (unsigned)l0 | ((unsigned)l1_ << 16);
            pl[1] = (unsigned)l2 | ((unsigned)l3 << 16);
        }
        *(uint4*)&BsH[brow * ASTR + bseg * 8] = rbh;
        *(uint4*)&BsL[brow * ASTR + bseg * 8] = rbl;
    };

    load_regs(0);
    store_smem(0);

    for (int kt = 0; kt < FIN / 32; kt++) {
        const int cur = kt & 1;
        __syncthreads();
        if (kt + 1 < FIN / 32) load_regs((kt + 1) * 32);

        const unsigned ash = smu + OFF_AH(cur);
        const unsigned asl = smu + OFF_AL(cur);
        const unsigned bsh = smu + OFF_BH(cur);
        const unsigned bsl = smu + OFF_BL(cur);

        #pragma unroll
        for (int ka = 0; ka < 2; ka++) {
            const int kc = ka * 16;
            unsigned a_hi[2][4], a_lo[2][4], b_hi[4][2], b_lo[4][2];
            #pragma unroll
            for (int ma = 0; ma < 2; ma++) {
                int r0 = warp_m * 32 + ma * 16;
                unsigned eoff = (unsigned)((r0 * ASTR + kc + lm_off) * 2);
                ldsm4(a_hi[ma], ash + eoff);
                ldsm4(a_lo[ma], asl + eoff);
            }
            #pragma unroll
            for (int p = 0; p < 2; p++) {
                int n0 = warp_n * 32 + p * 16;
                unsigned eoff = (unsigned)((n0 * ASTR + kc + lm_off) * 2);
                unsigned rh[4], rl[4];
                ldsm4(rh, bsh + eoff);
                ldsm4(rl, bsl + eoff);
                b_hi[2 * p][0] = rh[0]; b_hi[2 * p][1] = rh[2];
                b_hi[2 * p + 1][0] = rh[1]; b_hi[2 * p + 1][1] = rh[3];
                b_lo[2 * p][0] = rl[0]; b_lo[2 * p][1] = rl[2];
                b_lo[2 * p + 1][0] = rl[1]; b_lo[2 * p + 1][1] = rl[3];
            }
            #pragma unroll
            for (int ma = 0; ma < 2; ma++)
                #pragma unroll
                for (int na = 0; na < 4; na++) {
                    mma_bf16(acc[ma][na], a_hi[ma], b_hi[na]);
                    mma_bf16(acc[ma][na], a_hi[ma], b_lo[na]);
                    mma_bf16(acc[ma][na], a_lo[ma], b_hi[na]);
                }
        }

        if (kt + 1 < FIN / 32) store_smem(cur ^ 1);
    }

    // ---- epilogue: write h1 as fp16 ----
    #pragma unroll
    for (int ma = 0; ma < 2; ma++) {
        int r0 = bm0 + warp_m * 32 + ma * 16 + g;
        #pragma unroll
        for (int na = 0; na < 4; na++) {
            int c = warp_n * 32 + na * 8 + 2 * q;
            if (r0 < NN)
                *(__half2*)(g_h1h + (long)r0 * HC + c) =
                    __floats2half2_rn(acc[ma][na][0], acc[ma][na][1]);
            if (r0 + 8 < NN)
                *(__half2*)(g_h1h + (long)(r0 + 8) * HC + c) =
                    __floats2half2_rn(acc[ma][na][2], acc[ma][na][3]);
        }
    }

    // ---- fused alpha1 ----
    float as_c0[4], as_c1[4], ad_c0[4], ad_c1[4];
    #pragma unroll
    for (int na = 0; na < 4; na++) {
        int hh = warp_n * 4 + na;
        as_c0[na] = a_s[hh * 8 + 2 * q];
        as_c1[na] = a_s[hh * 8 + 2 * q + 1];
        ad_c0[na] = a_d[hh * 8 + 2 * q];
        ad_c1[na] = a_d[hh * 8 + 2 * q + 1];
    }
    #pragma unroll
    for (int ma = 0; ma < 2; ma++)
        #pragma unroll
        for (int rh = 0; rh < 2; rh++) {
            float s[4], d[4];
            #pragma unroll
            for (int na = 0; na < 4; na++) {
                float h0 = acc[ma][na][rh * 2 + 0];
                float h1v = acc[ma][na][rh * 2 + 1];
                s[na] = h0 * as_c0[na] + h1v * as_c1[na];
                d[na] = h0 * ad_c0[na] + h1v * ad_c1[na];
            }
            #pragma unroll
            for (int na = 0; na < 4; na++) {
                s[na] += __shfl_xor_sync(0xffffffffu, s[na], 1);
                s[na] += __shfl_xor_sync(0xffffffffu, s[na], 2);
                d[na] += __shfl_xor_sync(0xffffffffu, d[na], 1);
                d[na] += __shfl_xor_sync(0xffffffffu, d[na], 2);
            }
            int row = bm0 + warp_m * 32 + ma * 16 + rh * 8 + g;
            if (q == 0 && row < NN) {
                *(float4*)(g_as1 + row * H1 + warp_n * 4) = make_float4(s[0], s[1], s[2], s[3]);
                *(float4*)(g_ad1 + row * H1 + warp_n * 4) = make_float4(d[0], d[1], d[2], d[3]);
            }
        }
}

// ---------------- layer-1 CSR aggregation + ELU + fused alpha2 ----------------
__global__ void k_agg1(const float* __restrict__ b1) {
    int warp = (blockIdx.x * blockDim.x + threadIdx.x) >> 5;
    if (warp >= NN) return;
    int lane = threadIdx.x & 31;
    int qt = lane >> 3;
    int l = lane & 7;
    int n = warp;
    float adh = g_ad1[n * H1 + l];
    int beg = g_row[n], end = g_row[n + 1];
    float sp = 0.f;
    float A[8] = {0.f, 0.f, 0.f, 0.f, 0.f, 0.f, 0.f, 0.f};

    int j = beg + qt;
    for (; j + 4 < end; j += 8) {
        int s0 = g_csr[j], s1 = g_csr[j + 4];
        float e0 = g_as1[s0 * H1 + l];
        float e1 = g_as1[s1 * H1 + l];
        uint4 u0 = *(const uint4*)(g_h1h + (long)s0 * HC + l * 8);
        uint4 u1 = *(const uint4*)(g_h1h + (long)s1 * HC + l * 8);
        float p0 = __expf(lrelu(e0 + adh));
        float p1 = __expf(lrelu(e1 + adh));
        sp += p0 + p1;
        const __half2* hp0 = (const __half2*)&u0;
        const __half2* hp1 = (const __half2*)&u1;
        #pragma unroll
        for (int w = 0; w < 4; w++) {
            float2 f0 = __half22float2(hp0[w]);
            float2 f1 = __half22float2(hp1[w]);
            A[2 * w + 0] = fmaf(p0, f0.x, A[2 * w + 0]);
            A[2 * w + 1] = fmaf(p0, f0.y, A[2 * w + 1]);
            A[2 * w + 0] = fmaf(p1, f1.x, A[2 * w + 0]);
            A[2 * w + 1] = fmaf(p1, f1.y, A[2 * w + 1]);
        }
    }
    for (; j < end; j += 4) {
        int s0 = g_csr[j];
        float e0 = g_as1[s0 * H1 + l];
        uint4 u0 = *(const uint4*)(g_h1h + (long)s0 * HC + l * 8);
        float p0 = __expf(lrelu(e0 + adh));
        sp += p0;
        const __half2* hp0 = (const __half2*)&u0;
        #pragma unroll
        for (int w = 0; w < 4; w++) {
            float2 f0 = __half22float2(hp0[w]);
            A[2 * w + 0] = fmaf(p0, f0.x, A[2 * w + 0]);
            A[2 * w + 1] = fmaf(p0, f0.y, A[2 * w + 1]);
        }
    }
    #pragma unroll
    for (int i = 0; i < 8; i++) {
        A[i] += __shfl_xor_sync(0xffffffffu, A[i], 8);
        A[i] += __shfl_xor_sync(0xffffffffu, A[i], 16);
    }
    sp += __shfl_xor_sync(0xffffffffu, sp, 8);
    sp += __shfl_xor_sync(0xffffffffu, sp, 16);

    // epilogue computed in ALL lanes (quarters hold identical values)
    float inv = 1.0f / (sp + 1e-16f);
    float4 b0 = *(const float4*)(b1 + l * 8);
    float4 b1v = *(const float4*)(b1 + l * 8 + 4);
    float o[8];
    o[0] = A[0] * inv + b0.x; o[1] = A[1] * inv + b0.y;
    o[2] = A[2] * inv + b0.z; o[3] = A[3] * inv + b0.w;
    o[4] = A[4] * inv + b1v.x; o[5] = A[5] * inv + b1v.y;
    o[6] = A[6] * inv + b1v.z; o[7] = A[7] * inv + b1v.w;
    #pragma unroll
    for (int i = 0; i < 8; i++) o[i] = o[i] > 0.f ? o[i] : (expf(o[i]) - 1.f);

    if (qt == 0) {
        __half2 hv[4];
        #pragma unroll
        for (int w = 0; w < 4; w++) hv[w] = __floats2half2_rn(o[2 * w], o[2 * w + 1]);
        *(uint4*)(g_o1h + (long)n * HC + l * 8) = *(uint4*)hv;
    }

    // fused alpha2: as2[n] = o . w_s, ad2[n] = o . w_d
    float ps = 0.f, pd = 0.f;
    #pragma unroll
    for (int i = 0; i < 8; i++) {
        ps = fmaf(o[i], g_ws[l * 8 + i], ps);
        pd = fmaf(o[i], g_wd[l * 8 + i], pd);
    }
    ps += __shfl_xor_sync(0xffffffffu, ps, 1);
    ps += __shfl_xor_sync(0xffffffffu, ps, 2);
    ps += __shfl_xor_sync(0xffffffffu, ps, 4);
    pd += __shfl_xor_sync(0xffffffffu, pd, 1);
    pd += __shfl_xor_sync(0xffffffffu, pd, 2);
    pd += __shfl_xor_sync(0xffffffffu, pd, 4);
    if (lane == 0) {
        g_as2[n] = ps;
        g_ad2[n] = pd;
    }
}

// ---------------- layer-2: aggregate o over edges, then matvec W2 + log_softmax ----------------
__global__ void k_agg2(float* __restrict__ out, const float* __restrict__ b2,
                       const float* __restrict__ W2) {
    __shared__ float W2s[HC * NC];    // 10240 B
    __shared__ float buf[8][HC];      // 2048 B
    const int t = threadIdx.x;
    for (int i = t; i < HC * NC; i += 256) W2s[i] = W2[i];
    __syncthreads();

    int warp = (blockIdx.x * blockDim.x + t) >> 5;
    if (warp >= NN) return;
    int wloc = t >> 5;
    int lane = t & 31;
    int qt = lane >> 3;
    int l = lane & 7;
    int n = warp;
    float ad = g_ad2[n];
    int beg = g_row[n], end = g_row[n + 1];
    float sp = 0.f;
    float A[8] = {0.f, 0.f, 0.f, 0.f, 0.f, 0.f, 0.f, 0.f};

    int j = beg + qt;
    for (; j + 4 < end; j += 8) {
        int s0 = g_csr[j], s1 = g_csr[j + 4];
        float e0 = g_as2[s0], e1 = g_as2[s1];
        uint4 u0 = *(const uint4*)(g_o1h + (long)s0 * HC + l * 8);
        uint4 u1 = *(const uint4*)(g_o1h + (long)s1 * HC + l * 8);
        float p0 = __expf(lrelu(e0 + ad));
        float p1 = __expf(lrelu(e1 + ad));
        sp += p0 + p1;
        const __half2* hp0 = (const __half2*)&u0;
        const __half2* hp1 = (const __half2*)&u1;
        #pragma unroll
        for (int w = 0; w < 4; w++) {
            float2 f0 = __half22float2(hp0[w]);
            float2 f1 = __half22float2(hp1[w]);
            A[2 * w + 0] = fmaf(p0, f0.x, A[2 * w + 0]);
            A[2 * w + 1] = fmaf(p0, f0.y, A[2 * w + 1]);
            A[2 * w + 0] = fmaf(p1, f1.x, A[2 * w + 0]);
            A[2 * w + 1] = fmaf(p1, f1.y, A[2 * w + 1]);
        }
    }
    for (; j < end; j += 4) {
        int s0 = g_csr[j];
        float e0 = g_as2[s0];
        uint4 u0 = *(const uint4*)(g_o1h + (long)s0 * HC + l * 8);
        float p0 = __expf(lrelu(e0 + ad));
        sp += p0;
        const __half2* hp0 = (const __half2*)&u0;
        #pragma unroll
        for (int w = 0; w < 4; w++) {
            float2 f0 = __half22float2(hp0[w]);
            A[2 * w + 0] = fmaf(p0, f0.x, A[2 * w + 0]);
            A[2 * w + 1] = fmaf(p0, f0.y, A[2 * w + 1]);
        }
    }
    #pragma unroll
    for (int i = 0; i < 8; i++) {
        A[i] += __shfl_xor_sync(0xffffffffu, A[i], 8);
        A[i] += __shfl_xor_sync(0xffffffffu, A[i], 16);
    }
    sp += __shfl_xor_sync(0xffffffffu, sp, 8);
    sp += __shfl_xor_sync(0xffffffffu, sp, 16);

    float inv = 1.0f / (sp + 1e-16f);
    if (lane < 8) {
        #pragma unroll
        for (int i = 0; i < 8; i++) buf[wloc][l * 8 + i] = A[i] * inv;
    }
    __syncwarp();

    float va = 0.f, vb = 0.f;
    #pragma unroll 8
    for (int k = 0; k < HC; k++) {
        float bk = buf[wloc][k];
        va = fmaf(bk, W2s[k * NC + lane], va);
        if (lane < 8) vb = fmaf(bk, W2s[k * NC + 32 + lane], vb);
    }
    va += b2[lane];
    vb = (lane < 8) ? vb + b2[32 + lane] : -3.402823466e38f;

    float m = fmaxf(va, vb);
    #pragma unroll
    for (int off = 16; off > 0; off >>= 1)
        m = fmaxf(m, __shfl_xor_sync(0xffffffffu, m, off));
    float s = expf(va - m) + ((lane < 8) ? expf(vb - m) : 0.f);
    #pragma unroll
    for (int off = 16; off > 0; off >>= 1)
        s += __shfl_xor_sync(0xffffffffu, s, off);
    float lse = m + logf(s);
    float* op = out + (long)n * NC;
    op[lane] = va - lse;
    if (lane < 8) op[32 + lane] = vb - lse;
}

// ---------------- launch: fork-join two independent chains ----------------
extern "C" void kernel_launch(void* const* d_in, const int* in_sizes, int n_in,
                              void* d_out, int out_size) {
    const float* x    = (const float*)d_in[0];
    const void*  ei   = d_in[1];
    const float* W1   = (const float*)d_in[2];
    const float* as1  = (const float*)d_in[3];
    const float* ad1  = (const float*)d_in[4];
    const float* b1   = (const float*)d_in[5];
    const float* W2   = (const float*)d_in[6];
    const float* as2  = (const float*)d_in[7];
    const float* ad2  = (const float*)d_in[8];
    const float* b2   = (const float*)d_in[9];
    float*       out  = (float*)d_out;

    static cudaStream_t s2 = 0;
    static cudaEvent_t evFork = 0, evJoin = 0;
    if (s2 == 0) {
        cudaStreamCreateWithFlags(&s2, cudaStreamNonBlocking);
        cudaEventCreateWithFlags(&evFork, cudaEventDisableTiming);
        cudaEventCreateWithFlags(&evJoin, cudaEventDisableTiming);
        cudaFuncSetAttribute(k_gemm1, cudaFuncAttributeMaxDynamicSharedMemorySize, SMEM_G1);
    }

    const int TB = 256;

    // fork
    cudaEventRecord(evFork, 0);
    cudaStreamWaitEvent(s2, evFork, 0);

    // chain B (side stream): CSR build
    k_init   <<<(NN + TB - 1) / TB, TB, 0, s2>>>(ei);
    k_convert<<<(ETOT + TB - 1) / TB, TB, 0, s2>>>(ei);
    k_scan1  <<<NBLK, 1024, 0, s2>>>();
    k_scan2  <<<1, 32, 0, s2>>>();
    k_scan3  <<<(NN + TB - 1) / TB, TB, 0, s2>>>();
    k_scatter<<<(ETOT + TB - 1) / TB, TB, 0, s2>>>();
    cudaEventRecord(evJoin, s2);

    // chain A (origin stream): dense transform (wsd folded into prepW)
    k_prepW  <<<(FIN * HC + TB - 1) / TB, TB>>>(W1, W2, as2, ad2);
    k_gemm1  <<<(NN + 127) / 128, 256, SMEM_G1>>>(x, as1, ad1);

    // join
    cudaStreamWaitEvent(0, evJoin, 0);

    // serial tail (gemm2 algebraically eliminated)
    k_agg1   <<<(NN * 32 + TB - 1) / TB, TB>>>(b1);
    k_agg2   <<<(NN * 32 + TB - 1) / TB, TB>>>(out, b2, W2);
}